// round 2
// baseline (speedup 1.0000x reference)
#include <cuda_runtime.h>

#define NVOC  64
#define SD    32
#define FD    16
#define NB    256
#define SEQL  2048
#define NSTEP (SEQL - 1)          /* 2047 delta steps */
#define FSPLIT 1728               /* forward steps; backward covers the rest */

// LUT: per vocab id, 64 floats = [k_sem(32) | k_fast(16) | k_slow(16)]
__device__ float g_lut[NVOC * 64];
// inv(k.k + 1e-6): [0..63]=sem, [64..127]=fast, [128..191]=slow
__device__ float g_inv[3 * NVOC];
// forward-half state matrices
__device__ float g_Ms [NB * SD * SD];
__device__ float g_Mef[NB * FD * FD];
__device__ float g_Mes[NB * FD * FD];
// backward-half results: u at split, c_tail (packed [sem|fast|slow])
__device__ float g_u [NB * 64];
__device__ float g_ct[NB * 64];

// ---------------------------------------------------------------------------
// Kernel 1: per-token-id LUT (encoder + projections depend only on token id)
// ---------------------------------------------------------------------------
__global__ void lut_kernel(const float* __restrict__ embed,
                           const float* __restrict__ w1, const float* __restrict__ b1,
                           const float* __restrict__ w2, const float* __restrict__ b2,
                           const float* __restrict__ ln_g, const float* __restrict__ ln_b,
                           const float* __restrict__ sem_w, const float* __restrict__ sem_b,
                           const float* __restrict__ fast_w, const float* __restrict__ fast_b,
                           const float* __restrict__ slow_w, const float* __restrict__ slow_b)
{
    const int v = blockIdx.x;
    const int j = threadIdx.x;   // 0..127

    __shared__ float e[64];
    __shared__ float h1[128];
    __shared__ float x[64];
    __shared__ float xn[64];
    __shared__ float kk[64];

    if (j < 64) e[j] = embed[v * 64 + j];
    __syncthreads();

    {
        float acc = b1[j];
        #pragma unroll 8
        for (int d = 0; d < 64; d++) acc = fmaf(e[d], w1[d * 128 + j], acc);
        h1[j] = fmaxf(acc, 0.0f);
    }
    __syncthreads();

    if (j < 64) {
        float acc = b2[j];
        #pragma unroll 8
        for (int d = 0; d < 128; d++) acc = fmaf(h1[d], w2[d * 64 + j], acc);
        x[j] = e[j] + acc;
    }
    __syncthreads();

    if (j < 64) {
        float mu = 0.0f;
        #pragma unroll 8
        for (int d = 0; d < 64; d++) mu += x[d];
        mu *= (1.0f / 64.0f);
        float var = 0.0f;
        #pragma unroll 8
        for (int d = 0; d < 64; d++) { float dd = x[d] - mu; var = fmaf(dd, dd, var); }
        var *= (1.0f / 64.0f);
        float r = rsqrtf(var + 1e-5f);
        xn[j] = (x[j] - mu) * r * ln_g[j] + ln_b[j];
    }
    __syncthreads();

    if (j < 64) {
        float s;
        if (j < 32) {
            s = sem_b[j];
            #pragma unroll 8
            for (int d = 0; d < 64; d++) s = fmaf(xn[d], sem_w[d * SD + j], s);
        } else if (j < 48) {
            const int c = j - 32;
            s = fast_b[c];
            #pragma unroll 8
            for (int d = 0; d < 64; d++) s = fmaf(xn[d], fast_w[d * FD + c], s);
        } else {
            const int c = j - 48;
            s = slow_b[c];
            #pragma unroll 8
            for (int d = 0; d < 64; d++) s = fmaf(xn[d], slow_w[d * FD + c], s);
        }
        kk[j] = s;
        g_lut[v * 64 + j] = s;
    }
    __syncthreads();

    if (j < 3) {
        const int lo = (j == 0) ? 0 : (j == 1) ? 32 : 48;
        const int hi = (j == 0) ? 32 : (j == 1) ? 48 : 64;
        float s = 0.0f;
        for (int d = lo; d < hi; d++) s = fmaf(kk[d], kk[d], s);
        g_inv[j * NVOC + v] = 1.0f / (s + 1e-6f);
    }
}

// ---------------------------------------------------------------------------
// Backward adjoint scan (vector form), one thread per (batch, scale).
//   u_{j-1} = u_j - (w_j d_j /(kk+eps)) k_j ,  c += w_j d_j k_j ,  d_j = k_j.u_j
// ---------------------------------------------------------------------------
template<int DIM, int SCALE>
__device__ __forceinline__ void backward_scan(const int* __restrict__ sq, int b)
{
    const int off = (SCALE == 0) ? 0 : (SCALE == 1) ? 32 : 48;
    const float invL = 1.0f / 2048.0f;

    float u[DIM], c[DIM];
    {
        const int tq = __ldg(&sq[SEQL - 1]);                 // query token
        const float4* kp = reinterpret_cast<const float4*>(&g_lut[tq * 64 + off]);
        #pragma unroll
        for (int q = 0; q < DIM / 4; q++) {
            float4 kv = __ldg(&kp[q]);
            u[4*q+0] = kv.x; u[4*q+1] = kv.y; u[4*q+2] = kv.z; u[4*q+3] = kv.w;
        }
        #pragma unroll
        for (int i = 0; i < DIM; i++) c[i] = 0.0f;
    }

    // prefetch first step (j = NSTEP uses token NSTEP-1)
    int tok = __ldg(&sq[NSTEP - 1]);
    float k[DIM];
    {
        const float4* kp = reinterpret_cast<const float4*>(&g_lut[tok * 64 + off]);
        #pragma unroll
        for (int q = 0; q < DIM / 4; q++) {
            float4 kv = __ldg(&kp[q]);
            k[4*q+0] = kv.x; k[4*q+1] = kv.y; k[4*q+2] = kv.z; k[4*q+3] = kv.w;
        }
    }
    float ikk = __ldg(&g_inv[SCALE * NVOC + tok]);

    #pragma unroll 2
    for (int j = NSTEP; j > FSPLIT; j--) {
        // prefetch next iteration (j-1 uses token j-2; j-2 >= FSPLIT-1 >= 0)
        const int ntok = __ldg(&sq[j - 2]);
        float kn[DIM];
        {
            const float4* kp = reinterpret_cast<const float4*>(&g_lut[ntok * 64 + off]);
            #pragma unroll
            for (int q = 0; q < DIM / 4; q++) {
                float4 kv = __ldg(&kp[q]);
                kn[4*q+0] = kv.x; kn[4*q+1] = kv.y; kn[4*q+2] = kv.z; kn[4*q+3] = kv.w;
            }
        }
        const float ikkn = __ldg(&g_inv[SCALE * NVOC + ntok]);

        // d = k . u  (4 accumulators for ILP)
        float a0 = 0.f, a1 = 0.f, a2 = 0.f, a3 = 0.f;
        #pragma unroll
        for (int i = 0; i < DIM; i += 4) {
            a0 = fmaf(k[i+0], u[i+0], a0);
            a1 = fmaf(k[i+1], u[i+1], a1);
            a2 = fmaf(k[i+2], u[i+2], a2);
            a3 = fmaf(k[i+3], u[i+3], a3);
        }
        const float d = (a0 + a1) + (a2 + a3);

        float p;
        if (SCALE == 0)       p = d;
        else if (SCALE == 1)  p = d * ((float)j * invL);
        else                  p = d * sqrtf((float)j * invL);
        const float q = p * ikk;

        #pragma unroll
        for (int i = 0; i < DIM; i++) {
            c[i] = fmaf( p, k[i], c[i]);
            u[i] = fmaf(-q, k[i], u[i]);
        }

        #pragma unroll
        for (int i = 0; i < DIM; i++) k[i] = kn[i];
        ikk = ikkn;
    }

    float4* up = reinterpret_cast<float4*>(&g_u [b * 64 + off]);
    float4* cp = reinterpret_cast<float4*>(&g_ct[b * 64 + off]);
    #pragma unroll
    for (int q = 0; q < DIM / 4; q++) {
        up[q] = make_float4(u[4*q], u[4*q+1], u[4*q+2], u[4*q+3]);
        cp[q] = make_float4(c[4*q], c[4*q+1], c[4*q+2], c[4*q+3]);
    }
}

// ---------------------------------------------------------------------------
// Kernel 2: forward matrix scan (blocks 0..255) + backward adjoint (256..261)
// Forward block: 128 threads, column-split x2:
//   warps 0-1: Ms (thread = (row, half) of 32x32), warp 2: Mef, warp 3: Mes
// ---------------------------------------------------------------------------
__global__ void __launch_bounds__(128)
scan_kernel(const int* __restrict__ seq)
{
    if (blockIdx.x >= NB) {
        const int bi = blockIdx.x - NB;          // 0..5
        const int scale = bi >> 1;
        const int b = (bi & 1) * 128 + threadIdx.x;
        const int* sq = seq + b * SEQL;
        if (scale == 0)      backward_scan<SD, 0>(sq, b);
        else if (scale == 1) backward_scan<FD, 1>(sq, b);
        else                 backward_scan<FD, 2>(sq, b);
        return;
    }

    __shared__ float s_lut[NVOC * 64];
    __shared__ float s_inv[3 * NVOC];
    __shared__ int   s_seq[FSPLIT + 2];

    const int b   = blockIdx.x;
    const int tid = threadIdx.x;

    for (int i = tid; i < NVOC * 64; i += 128) s_lut[i] = g_lut[i];
    for (int i = tid; i < 3 * NVOC;  i += 128) s_inv[i] = g_inv[i];
    {
        const int* sq = seq + b * SEQL;
        for (int i = tid; i < FSPLIT; i += 128) s_seq[i] = sq[i];
        if (tid == 0) { s_seq[FSPLIT] = 0; s_seq[FSPLIT + 1] = 0; }
    }
    __syncthreads();

    const int w    = tid >> 5;
    const int lane = tid & 31;

    if (w < 2) {
        // ----------------- Ms 32x32, w = 1, column-split x2 -----------------
        const int row = w * 16 + (lane >> 1);
        const int h   = lane & 1;
        const int coff = h * 16;

        float m[16];
        #pragma unroll
        for (int j = 0; j < 16; j++) m[j] = 0.0f;

        int tok = s_seq[0];
        float k[16], ki, ikk;
        {
            const float4* kp = reinterpret_cast<const float4*>(&s_lut[tok * 64 + coff]);
            #pragma unroll
            for (int q = 0; q < 4; q++) {
                float4 kv = kp[q];
                k[4*q+0] = kv.x; k[4*q+1] = kv.y; k[4*q+2] = kv.z; k[4*q+3] = kv.w;
            }
            ki  = s_lut[tok * 64 + row];
            ikk = s_inv[tok];
        }

        #pragma unroll 2
        for (int t = 0; t < FSPLIT; t++) {
            // prefetch t+1
            const int ntok = s_seq[t + 1];
            float kn[16];
            {
                const float4* kp = reinterpret_cast<const float4*>(&s_lut[ntok * 64 + coff]);
                #pragma unroll
                for (int q = 0; q < 4; q++) {
                    float4 kv = kp[q];
                    kn[4*q+0] = kv.x; kn[4*q+1] = kv.y; kn[4*q+2] = kv.z; kn[4*q+3] = kv.w;
                }
            }
            const float kin  = s_lut[ntok * 64 + row];
            const float ikkn = s_inv[ntok];

            float a0 = 0.f, a1 = 0.f, a2 = 0.f, a3 = 0.f;
            #pragma unroll
            for (int j = 0; j < 16; j += 4) {
                a0 = fmaf(m[j+0], k[j+0], a0);
                a1 = fmaf(m[j+1], k[j+1], a1);
                a2 = fmaf(m[j+2], k[j+2], a2);
                a3 = fmaf(m[j+3], k[j+3], a3);
            }
            float part = (a0 + a1) + (a2 + a3);
            const float vp = part + __shfl_xor_sync(0xffffffffu, part, 1);
            const float dv = fmaf(-vp, ikk, ki);
            #pragma unroll
            for (int j = 0; j < 16; j++) m[j] = fmaf(dv, k[j], m[j]);

            #pragma unroll
            for (int j = 0; j < 16; j++) k[j] = kn[j];
            ki = kin; ikk = ikkn;
        }

        float4* dst = reinterpret_cast<float4*>(&g_Ms[(b * SD + row) * SD + coff]);
        #pragma unroll
        for (int q = 0; q < 4; q++)
            dst[q] = make_float4(m[4*q], m[4*q+1], m[4*q+2], m[4*q+3]);
    } else {
        // ----------------- Mef (warp 2) / Mes (warp 3), split x2 ------------
        const bool isf = (w == 2);
        const int  row = lane >> 1;
        const int  h   = lane & 1;
        const int  off = isf ? 32 : 48;
        const int  coff = off + h * 8;
        const float* invp = &s_inv[isf ? NVOC : 2 * NVOC];
        const float invL = 1.0f / 2048.0f;

        float m[8];
        #pragma unroll
        for (int j = 0; j < 8; j++) m[j] = 0.0f;

        int tok = s_seq[0];
        float k[8], kr, ikk;
        {
            const float4* kp = reinterpret_cast<const float4*>(&s_lut[tok * 64 + coff]);
            #pragma unroll
            for (int q = 0; q < 2; q++) {
                float4 kv = kp[q];
                k[4*q+0] = kv.x; k[4*q+1] = kv.y; k[4*q+2] = kv.z; k[4*q+3] = kv.w;
            }
            kr  = s_lut[tok * 64 + off + row];
            ikk = invp[tok];
        }

        #pragma unroll 2
        for (int t = 0; t < FSPLIT; t++) {
            const int ntok = s_seq[t + 1];
            float kn[8];
            {
                const float4* kp = reinterpret_cast<const float4*>(&s_lut[ntok * 64 + coff]);
                #pragma unroll
                for (int q = 0; q < 2; q++) {
                    float4 kv = kp[q];
                    kn[4*q+0] = kv.x; kn[4*q+1] = kv.y; kn[4*q+2] = kv.z; kn[4*q+3] = kv.w;
                }
            }
            const float krn  = s_lut[ntok * 64 + off + row];
            const float ikkn = invp[ntok];

            float wt = (float)(t + 1) * invL;
            if (!isf) wt = sqrtf(wt);

            float a0 = 0.f, a1 = 0.f;
            #pragma unroll
            for (int j = 0; j < 8; j += 2) {
                a0 = fmaf(m[j+0], k[j+0], a0);
                a1 = fmaf(m[j+1], k[j+1], a1);
            }
            float part = a0 + a1;
            const float vp  = part + __shfl_xor_sync(0xffffffffu, part, 1);
            const float dv  = fmaf(-vp, ikk, kr);
            const float wdv = wt * dv;
            #pragma unroll
            for (int j = 0; j < 8; j++) m[j] = fmaf(wdv, k[j], m[j]);

            #pragma unroll
            for (int j = 0; j < 8; j++) k[j] = kn[j];
            kr = krn; ikk = ikkn;
        }

        float* base = isf ? g_Mef : g_Mes;
        float4* dst = reinterpret_cast<float4*>(&base[(b * FD + row) * FD + h * 8]);
        #pragma unroll
        for (int q = 0; q < 2; q++)
            dst[q] = make_float4(m[4*q], m[4*q+1], m[4*q+2], m[4*q+3]);
    }
}

// ---------------------------------------------------------------------------
// Kernel 3: join  c = M_F u_F + c_tail , then readout GEMM
// ---------------------------------------------------------------------------
__global__ void __launch_bounds__(64)
join_kernel(const float* __restrict__ out_w, const float* __restrict__ out_b,
            float* __restrict__ out)
{
    __shared__ float su[64];
    __shared__ float sc[64];
    const int b   = blockIdx.x;
    const int tid = threadIdx.x;

    su[tid] = g_u[b * 64 + tid];
    __syncthreads();

    float acc = g_ct[b * 64 + tid];
    if (tid < 32) {
        const float4* mp = reinterpret_cast<const float4*>(&g_Ms[(b * SD + tid) * SD]);
        #pragma unroll
        for (int q = 0; q < 8; q++) {
            float4 mv = mp[q];
            acc = fmaf(mv.x, su[4*q+0], acc);
            acc = fmaf(mv.y, su[4*q+1], acc);
            acc = fmaf(mv.z, su[4*q+2], acc);
            acc = fmaf(mv.w, su[4*q+3], acc);
        }
    } else if (tid < 48) {
        const int r = tid - 32;
        const float4* mp = reinterpret_cast<const float4*>(&g_Mef[(b * FD + r) * FD]);
        #pragma unroll
        for (int q = 0; q < 4; q++) {
            float4 mv = mp[q];
            acc = fmaf(mv.x, su[32 + 4*q+0], acc);
            acc = fmaf(mv.y, su[32 + 4*q+1], acc);
            acc = fmaf(mv.z, su[32 + 4*q+2], acc);
            acc = fmaf(mv.w, su[32 + 4*q+3], acc);
        }
    } else {
        const int r = tid - 48;
        const float4* mp = reinterpret_cast<const float4*>(&g_Mes[(b * FD + r) * FD]);
        #pragma unroll
        for (int q = 0; q < 4; q++) {
            float4 mv = mp[q];
            acc = fmaf(mv.x, su[48 + 4*q+0], acc);
            acc = fmaf(mv.y, su[48 + 4*q+1], acc);
            acc = fmaf(mv.z, su[48 + 4*q+2], acc);
            acc = fmaf(mv.w, su[48 + 4*q+3], acc);
        }
    }
    sc[tid] = acc;
    __syncthreads();

    float o = out_b[tid];
    #pragma unroll 8
    for (int d = 0; d < 64; d++) o = fmaf(sc[d], out_w[d * 64 + tid], o);
    out[b * 64 + tid] = o;
}

// ---------------------------------------------------------------------------
extern "C" void kernel_launch(void* const* d_in, const int* in_sizes, int n_in,
                              void* d_out, int out_size)
{
    const int*   seq    = (const int*)  d_in[0];
    const float* embed  = (const float*)d_in[1];
    const float* w1     = (const float*)d_in[2];
    const float* b1     = (const float*)d_in[3];
    const float* w2     = (const float*)d_in[4];
    const float* b2     = (const float*)d_in[5];
    const float* ln_g   = (const float*)d_in[6];
    const float* ln_b   = (const float*)d_in[7];
    const float* sem_w  = (const float*)d_in[8];
    const float* sem_b  = (const float*)d_in[9];
    const float* fast_w = (const float*)d_in[10];
    const float* fast_b = (const float*)d_in[11];
    const float* slow_w = (const float*)d_in[12];
    const float* slow_b = (const float*)d_in[13];
    const float* out_w  = (const float*)d_in[14];
    const float* out_b  = (const float*)d_in[15];
    float* out = (float*)d_out;

    lut_kernel<<<NVOC, 128>>>(embed, w1, b1, w2, b2, ln_g, ln_b,
                              sem_w, sem_b, fast_w, fast_b, slow_w, slow_b);
    scan_kernel<<<NB + 6, 128>>>(seq);
    join_kernel<<<NB, 64>>>(out_w, out_b, out);
}

// round 3
// speedup vs baseline: 2.4561x; 2.4561x over previous
#include <cuda_runtime.h>

#define NVOC  64
#define SD    32
#define FD    16
#define NB    256
#define SEQL  2048
#define NSTEP 2047                /* delta steps, t = 0..2046, token = sq[t] */
#define FSPLIT 1280               /* forward covers t in [0, FSPLIT) */
#define NFWD  128                 /* forward blocks, 2 batches each */
#define NBWD  8                   /* backward blocks, 32 batches each */
#define CHUNK 64

// LUT: per vocab id, 64 floats = [k_sem(32) | k_fast(16) | k_slow(16)]
__device__ float g_lut[NVOC * 64];
// inv(k.k + 1e-6): [0..63]=sem, [64..127]=fast, [128..191]=slow
__device__ float g_inv[3 * NVOC];
// forward-half state matrices
__device__ float g_Ms [NB * SD * SD];
__device__ float g_Mef[NB * FD * FD];
__device__ float g_Mes[NB * FD * FD];
// backward-half results: u at split, c_tail (packed [sem|fast|slow])
__device__ float g_u [NB * 64];
__device__ float g_ct[NB * 64];

// ---------------------------------------------------------------------------
// Kernel 1: per-token-id LUT (encoder + projections depend only on token id)
// ---------------------------------------------------------------------------
__global__ void lut_kernel(const float* __restrict__ embed,
                           const float* __restrict__ w1, const float* __restrict__ b1,
                           const float* __restrict__ w2, const float* __restrict__ b2,
                           const float* __restrict__ ln_g, const float* __restrict__ ln_b,
                           const float* __restrict__ sem_w, const float* __restrict__ sem_b,
                           const float* __restrict__ fast_w, const float* __restrict__ fast_b,
                           const float* __restrict__ slow_w, const float* __restrict__ slow_b)
{
    const int v = blockIdx.x;
    const int j = threadIdx.x;   // 0..127

    __shared__ float e[64];
    __shared__ float h1[128];
    __shared__ float x[64];
    __shared__ float xn[64];
    __shared__ float kk[64];

    if (j < 64) e[j] = embed[v * 64 + j];
    __syncthreads();

    {
        float acc = b1[j];
        #pragma unroll 8
        for (int d = 0; d < 64; d++) acc = fmaf(e[d], w1[d * 128 + j], acc);
        h1[j] = fmaxf(acc, 0.0f);
    }
    __syncthreads();

    if (j < 64) {
        float acc = b2[j];
        #pragma unroll 8
        for (int d = 0; d < 128; d++) acc = fmaf(h1[d], w2[d * 64 + j], acc);
        x[j] = e[j] + acc;
    }
    __syncthreads();

    if (j < 64) {
        float mu = 0.0f;
        #pragma unroll 8
        for (int d = 0; d < 64; d++) mu += x[d];
        mu *= (1.0f / 64.0f);
        float var = 0.0f;
        #pragma unroll 8
        for (int d = 0; d < 64; d++) { float dd = x[d] - mu; var = fmaf(dd, dd, var); }
        var *= (1.0f / 64.0f);
        float r = rsqrtf(var + 1e-5f);
        xn[j] = (x[j] - mu) * r * ln_g[j] + ln_b[j];
    }
    __syncthreads();

    if (j < 64) {
        float s;
        if (j < 32) {
            s = sem_b[j];
            #pragma unroll 8
            for (int d = 0; d < 64; d++) s = fmaf(xn[d], sem_w[d * SD + j], s);
        } else if (j < 48) {
            const int c = j - 32;
            s = fast_b[c];
            #pragma unroll 8
            for (int d = 0; d < 64; d++) s = fmaf(xn[d], fast_w[d * FD + c], s);
        } else {
            const int c = j - 48;
            s = slow_b[c];
            #pragma unroll 8
            for (int d = 0; d < 64; d++) s = fmaf(xn[d], slow_w[d * FD + c], s);
        }
        kk[j] = s;
        g_lut[v * 64 + j] = s;
    }
    __syncthreads();

    if (j < 3) {
        const int lo = (j == 0) ? 0 : (j == 1) ? 32 : 48;
        const int hi = (j == 0) ? 32 : (j == 1) ? 48 : 64;
        float s = 0.0f;
        for (int d = lo; d < hi; d++) s = fmaf(kk[d], kk[d], s);
        g_inv[j * NVOC + v] = 1.0f / (s + 1e-6f);
    }
}

// ---------------------------------------------------------------------------
// Backward chunk: adjoint vector recurrence over tt = t_hi .. t_lo (descending)
//   d = k.u ; p = w*d ; c += p*k ; u -= (p*ikk)*k
// lut rows padded to stride 68 floats (bank-conflict mitigation for gathers)
// ---------------------------------------------------------------------------
template<int DIM, int SCALE>
__device__ __forceinline__ void bw_chunk(float* __restrict__ u, float* __restrict__ c,
                                         int t_hi, int t_lo,
                                         const float* __restrict__ lut,
                                         const float* __restrict__ inv,
                                         const int* __restrict__ tokrow)
{
    const int off = (SCALE == 0) ? 0 : (SCALE == 1) ? 32 : 48;
    const float invL = 1.0f / 2048.0f;

    #pragma unroll 2
    for (int tt = t_hi; tt >= t_lo; tt--) {
        const int tok = tokrow[tt - t_lo];
        const float4* kb = reinterpret_cast<const float4*>(&lut[tok * 68 + off]);
        float k[DIM];
        #pragma unroll
        for (int q = 0; q < DIM / 4; q++) {
            float4 v = kb[q];
            k[4*q+0] = v.x; k[4*q+1] = v.y; k[4*q+2] = v.z; k[4*q+3] = v.w;
        }
        const float ikk = inv[SCALE * 64 + tok];

        float a0 = 0.f, a1 = 0.f, a2 = 0.f, a3 = 0.f;
        #pragma unroll
        for (int i = 0; i < DIM; i += 4) {
            a0 = fmaf(k[i+0], u[i+0], a0);
            a1 = fmaf(k[i+1], u[i+1], a1);
            a2 = fmaf(k[i+2], u[i+2], a2);
            a3 = fmaf(k[i+3], u[i+3], a3);
        }
        const float d = (a0 + a1) + (a2 + a3);

        float p;
        if (SCALE == 0)       p = d;
        else if (SCALE == 1)  p = d * ((float)(tt + 1) * invL);
        else                  p = d * sqrtf((float)(tt + 1) * invL);
        const float qq = p * ikk;

        #pragma unroll
        for (int i = 0; i < DIM; i++) {
            c[i] = fmaf( p, k[i], c[i]);
            u[i] = fmaf(-qq, k[i], u[i]);
        }
    }
}

// ---------------------------------------------------------------------------
// Kernel 2: one wave of 136 blocks
//   blocks 0..127  : forward matrix scan, 2 batches/block
//                    warps 0-1 -> batch 2*bid, warps 2-3 -> batch 2*bid+1
//                    even warp: Ms row/lane; odd warp: Mef (lanes<16) / Mes
//   blocks 128..135: backward adjoint, 32 batches/block
//                    warp0=sem, warp1=fast, warp2=slow, warp3 helps staging
// ---------------------------------------------------------------------------
__global__ void __launch_bounds__(128)
scan_kernel(const int* __restrict__ seq)
{
    __shared__ __align__(16) char raw[28672];
    const int tid  = threadIdx.x;
    const int w    = tid >> 5;
    const int lane = tid & 31;

    if (blockIdx.x < NFWD) {
        // ------------------------- FORWARD -------------------------
        float* s_lut = (float*)raw;                 // 64*64 = 16384 B
        float* s_inv = (float*)(raw + 16384);       // 192 floats
        int*   s_seq = (int*)  (raw + 17152);       // 2 * (FSPLIT+1) ints

        const int b0 = blockIdx.x * 2;
        for (int i = tid; i < NVOC * 64; i += 128) s_lut[i] = g_lut[i];
        for (int i = tid; i < 3 * NVOC;  i += 128) s_inv[i] = g_inv[i];
        for (int i = tid; i < FSPLIT; i += 128) {
            s_seq[i]              = seq[ b0      * SEQL + i];
            s_seq[FSPLIT + 1 + i] = seq[(b0 + 1) * SEQL + i];
        }
        if (tid == 0) { s_seq[FSPLIT] = 0; s_seq[2 * FSPLIT + 1] = 0; }
        __syncthreads();

        const int  bsel = w >> 1;
        const int  b    = b0 + bsel;
        const int* sq   = s_seq + bsel * (FSPLIT + 1);

        if ((w & 1) == 0) {
            // ---- Ms 32x32, w=1, lane = row ----
            float m[SD];
            #pragma unroll
            for (int j = 0; j < SD; j++) m[j] = 0.0f;

            int tok = sq[0];
            float k[SD], ki, ikk;
            {
                const float4* kp = reinterpret_cast<const float4*>(&s_lut[tok * 64]);
                #pragma unroll
                for (int q = 0; q < 8; q++) {
                    float4 v = kp[q];
                    k[4*q+0] = v.x; k[4*q+1] = v.y; k[4*q+2] = v.z; k[4*q+3] = v.w;
                }
                ki  = s_lut[tok * 64 + lane];
                ikk = s_inv[tok];
            }

            #pragma unroll 2
            for (int t = 0; t < FSPLIT; t++) {
                const int ntok = sq[t + 1];
                float kn[SD], kin, ikkn;
                {
                    const float4* kp = reinterpret_cast<const float4*>(&s_lut[ntok * 64]);
                    #pragma unroll
                    for (int q = 0; q < 8; q++) {
                        float4 v = kp[q];
                        kn[4*q+0] = v.x; kn[4*q+1] = v.y; kn[4*q+2] = v.z; kn[4*q+3] = v.w;
                    }
                    kin  = s_lut[ntok * 64 + lane];
                    ikkn = s_inv[ntok];
                }

                float a0 = 0.f, a1 = 0.f, a2 = 0.f, a3 = 0.f;
                #pragma unroll
                for (int j = 0; j < SD; j += 4) {
                    a0 = fmaf(m[j+0], k[j+0], a0);
                    a1 = fmaf(m[j+1], k[j+1], a1);
                    a2 = fmaf(m[j+2], k[j+2], a2);
                    a3 = fmaf(m[j+3], k[j+3], a3);
                }
                const float vp = (a0 + a1) + (a2 + a3);
                const float dv = fmaf(-vp, ikk, ki);
                #pragma unroll
                for (int j = 0; j < SD; j++) m[j] = fmaf(dv, k[j], m[j]);

                #pragma unroll
                for (int j = 0; j < SD; j++) k[j] = kn[j];
                ki = kin; ikk = ikkn;
            }

            float4* dst = reinterpret_cast<float4*>(&g_Ms[(b * SD + lane) * SD]);
            #pragma unroll
            for (int q = 0; q < 8; q++)
                dst[q] = make_float4(m[4*q], m[4*q+1], m[4*q+2], m[4*q+3]);
        } else {
            // ---- Mef (lanes 0-15) / Mes (lanes 16-31), lane%16 = row ----
            const bool isf = (lane < 16);
            const int  r   = lane & 15;
            const int  off = isf ? 32 : 48;
            const float* invp = s_inv + (isf ? 64 : 128);
            const float invL = 1.0f / 2048.0f;

            float m[FD];
            #pragma unroll
            for (int j = 0; j < FD; j++) m[j] = 0.0f;

            int tok = sq[0];
            float k[FD], kr, ikk;
            {
                const float4* kp = reinterpret_cast<const float4*>(&s_lut[tok * 64 + off]);
                #pragma unroll
                for (int q = 0; q < 4; q++) {
                    float4 v = kp[q];
                    k[4*q+0] = v.x; k[4*q+1] = v.y; k[4*q+2] = v.z; k[4*q+3] = v.w;
                }
                kr  = s_lut[tok * 64 + off + r];
                ikk = invp[tok];
            }

            #pragma unroll 2
            for (int t = 0; t < FSPLIT; t++) {
                const int ntok = sq[t + 1];
                float kn[FD], krn, ikkn;
                {
                    const float4* kp = reinterpret_cast<const float4*>(&s_lut[ntok * 64 + off]);
                    #pragma unroll
                    for (int q = 0; q < 4; q++) {
                        float4 v = kp[q];
                        kn[4*q+0] = v.x; kn[4*q+1] = v.y; kn[4*q+2] = v.z; kn[4*q+3] = v.w;
                    }
                    krn  = s_lut[ntok * 64 + off + r];
                    ikkn = invp[ntok];
                }

                float wt = (float)(t + 1) * invL;
                if (!isf) wt = sqrtf(wt);

                float a0 = 0.f, a1 = 0.f, a2 = 0.f, a3 = 0.f;
                #pragma unroll
                for (int j = 0; j < FD; j += 4) {
                    a0 = fmaf(m[j+0], k[j+0], a0);
                    a1 = fmaf(m[j+1], k[j+1], a1);
                    a2 = fmaf(m[j+2], k[j+2], a2);
                    a3 = fmaf(m[j+3], k[j+3], a3);
                }
                const float vp  = (a0 + a1) + (a2 + a3);
                const float dv  = fmaf(-vp, ikk, kr);
                const float wdv = wt * dv;
                #pragma unroll
                for (int j = 0; j < FD; j++) m[j] = fmaf(wdv, k[j], m[j]);

                #pragma unroll
                for (int j = 0; j < FD; j++) k[j] = kn[j];
                kr = krn; ikk = ikkn;
            }

            float* base = isf ? g_Mef : g_Mes;
            float4* dst = reinterpret_cast<float4*>(&base[(b * FD + r) * FD]);
            #pragma unroll
            for (int q = 0; q < 4; q++)
                dst[q] = make_float4(m[4*q], m[4*q+1], m[4*q+2], m[4*q+3]);
        }
    } else {
        // ------------------------- BACKWARD -------------------------
        float* s_lutP = (float*)raw;                 // 64 * 68 floats = 17408 B
        float* s_invB = (float*)(raw + 17408);       // 192 floats
        int (*s_tok)[65] = (int(*)[65])(raw + 18176);// 32 * 65 ints

        const int bb = blockIdx.x - NFWD;            // 0..7
        const int b0 = bb * 32;
        const int b  = b0 + lane;

        for (int i = tid; i < NVOC * 64; i += 128) {
            const int rrow = i >> 6, cc = i & 63;
            s_lutP[rrow * 68 + cc] = g_lut[i];
        }
        for (int i = tid; i < 3 * NVOC; i += 128) s_invB[i] = g_inv[i];
        __syncthreads();

        float u[SD], c[SD];
        const int dimw = (w == 0) ? SD : FD;
        if (w < 3) {
            const int off = (w == 0) ? 0 : (w == 1) ? 32 : 48;
            const int tokq = __ldg(&seq[b * SEQL + SEQL - 1]);
            for (int i = 0; i < dimw; i++) {
                u[i] = s_lutP[tokq * 68 + off + i];
                c[i] = 0.0f;
            }
        }

        int t = NSTEP - 1;                           // 2046
        while (t >= FSPLIT) {
            int c_lo = t - (CHUNK - 1);
            if (c_lo < FSPLIT) c_lo = FSPLIT;

            for (int idx = tid; idx < 32 * CHUNK; idx += 128) {
                const int bbx = idx >> 6, ii = idx & 63;
                s_tok[bbx][ii] = seq[(b0 + bbx) * SEQL + c_lo + ii];
            }
            __syncthreads();

            if (w == 0)      bw_chunk<SD, 0>(u, c, t, c_lo, s_lutP, s_invB, s_tok[lane]);
            else if (w == 1) bw_chunk<FD, 1>(u, c, t, c_lo, s_lutP, s_invB, s_tok[lane]);
            else if (w == 2) bw_chunk<FD, 2>(u, c, t, c_lo, s_lutP, s_invB, s_tok[lane]);
            __syncthreads();

            t = c_lo - 1;
        }

        if (w < 3) {
            const int off = (w == 0) ? 0 : (w == 1) ? 32 : 48;
            float4* up = reinterpret_cast<float4*>(&g_u [b * 64 + off]);
            float4* cp = reinterpret_cast<float4*>(&g_ct[b * 64 + off]);
            for (int q = 0; q < dimw / 4; q++) {
                up[q] = make_float4(u[4*q], u[4*q+1], u[4*q+2], u[4*q+3]);
                cp[q] = make_float4(c[4*q], c[4*q+1], c[4*q+2], c[4*q+3]);
            }
        }
    }
}

// ---------------------------------------------------------------------------
// Kernel 3: join  c = M_F u_F + c_tail , then readout GEMM
// ---------------------------------------------------------------------------
__global__ void __launch_bounds__(64)
join_kernel(const float* __restrict__ out_w, const float* __restrict__ out_b,
            float* __restrict__ out)
{
    __shared__ float su[64];
    __shared__ float sc[64];
    const int b   = blockIdx.x;
    const int tid = threadIdx.x;

    su[tid] = g_u[b * 64 + tid];
    __syncthreads();

    float acc = g_ct[b * 64 + tid];
    if (tid < 32) {
        const float4* mp = reinterpret_cast<const float4*>(&g_Ms[(b * SD + tid) * SD]);
        #pragma unroll
        for (int q = 0; q < 8; q++) {
            float4 mv = mp[q];
            acc = fmaf(mv.x, su[4*q+0], acc);
            acc = fmaf(mv.y, su[4*q+1], acc);
            acc = fmaf(mv.z, su[4*q+2], acc);
            acc = fmaf(mv.w, su[4*q+3], acc);
        }
    } else if (tid < 48) {
        const int r = tid - 32;
        const float4* mp = reinterpret_cast<const float4*>(&g_Mef[(b * FD + r) * FD]);
        #pragma unroll
        for (int q = 0; q < 4; q++) {
            float4 mv = mp[q];
            acc = fmaf(mv.x, su[32 + 4*q+0], acc);
            acc = fmaf(mv.y, su[32 + 4*q+1], acc);
            acc = fmaf(mv.z, su[32 + 4*q+2], acc);
            acc = fmaf(mv.w, su[32 + 4*q+3], acc);
        }
    } else {
        const int r = tid - 48;
        const float4* mp = reinterpret_cast<const float4*>(&g_Mes[(b * FD + r) * FD]);
        #pragma unroll
        for (int q = 0; q < 4; q++) {
            float4 mv = mp[q];
            acc = fmaf(mv.x, su[48 + 4*q+0], acc);
            acc = fmaf(mv.y, su[48 + 4*q+1], acc);
            acc = fmaf(mv.z, su[48 + 4*q+2], acc);
            acc = fmaf(mv.w, su[48 + 4*q+3], acc);
        }
    }
    sc[tid] = acc;
    __syncthreads();

    float o = out_b[tid];
    #pragma unroll 8
    for (int d = 0; d < 64; d++) o = fmaf(sc[d], out_w[d * 64 + tid], o);
    out[b * 64 + tid] = o;
}

// ---------------------------------------------------------------------------
extern "C" void kernel_launch(void* const* d_in, const int* in_sizes, int n_in,
                              void* d_out, int out_size)
{
    const int*   seq    = (const int*)  d_in[0];
    const float* embed  = (const float*)d_in[1];
    const float* w1     = (const float*)d_in[2];
    const float* b1     = (const float*)d_in[3];
    const float* w2     = (const float*)d_in[4];
    const float* b2     = (const float*)d_in[5];
    const float* ln_g   = (const float*)d_in[6];
    const float* ln_b   = (const float*)d_in[7];
    const float* sem_w  = (const float*)d_in[8];
    const float* sem_b  = (const float*)d_in[9];
    const float* fast_w = (const float*)d_in[10];
    const float* fast_b = (const float*)d_in[11];
    const float* slow_w = (const float*)d_in[12];
    const float* slow_b = (const float*)d_in[13];
    const float* out_w  = (const float*)d_in[14];
    const float* out_b  = (const float*)d_in[15];
    float* out = (float*)d_out;

    lut_kernel<<<NVOC, 128>>>(embed, w1, b1, w2, b2, ln_g, ln_b,
                              sem_w, sem_b, fast_w, fast_b, slow_w, slow_b);
    scan_kernel<<<NFWD + NBWD, 128>>>(seq);
    join_kernel<<<NB, 64>>>(out_w, out_b, out);
}

// round 4
// speedup vs baseline: 2.5767x; 1.0491x over previous
#include <cuda_runtime.h>

#define NVOC   64
#define SD     32
#define FD     16
#define NB     256
#define SEQL   2048
#define NSTEP  2047               /* delta steps, t = 0..2046 */
#define FSPLIT 1152               /* forward covers t in [0, FSPLIT), mult of 64 */
#define NFWD   128                /* forward blocks, 2 batches each */
#define NBWD   8                  /* backward blocks, 32 batches each */
#define NCHUNK ((NSTEP - FSPLIT + 63) / 64)

typedef unsigned long long u64t;

// ---------------- packed f32x2 helpers ----------------
__device__ __forceinline__ u64t ffma2(u64t a, u64t b, u64t c) {
    u64t d; asm("fma.rn.f32x2 %0, %1, %2, %3;" : "=l"(d) : "l"(a), "l"(b), "l"(c)); return d;
}
__device__ __forceinline__ u64t fadd2(u64t a, u64t b) {
    u64t d; asm("add.rn.f32x2 %0, %1, %2;" : "=l"(d) : "l"(a), "l"(b)); return d;
}
__device__ __forceinline__ u64t pack2(float lo, float hi) {
    u64t d; asm("mov.b64 %0, {%1, %2};" : "=l"(d) : "f"(lo), "f"(hi)); return d;
}
__device__ __forceinline__ void unpack2(u64t a, float& lo, float& hi) {
    asm("mov.b64 {%0, %1}, %2;" : "=f"(lo), "=f"(hi) : "l"(a));
}

// LUT: per vocab id, 64 floats = [k_sem(32) | k_fast(16) | k_slow(16)]
__device__ float g_lut[NVOC * 64];
// inv(k.k + 1e-6): [0..63]=sem, [64..127]=fast, [128..191]=slow
__device__ float g_inv[3 * NVOC];
// forward-half state matrices
__device__ float g_Ms [NB * SD * SD];
__device__ float g_Mef[NB * FD * FD];
__device__ float g_Mes[NB * FD * FD];
// backward-half results: u at split, c_tail (packed [sem|fast|slow])
__device__ float g_u [NB * 64];
__device__ float g_ct[NB * 64];

// ---------------------------------------------------------------------------
// Kernel 1: per-token-id LUT. 8 accumulators + full unroll -> deep MLP.
// ---------------------------------------------------------------------------
__global__ void lut_kernel(const float* __restrict__ embed,
                           const float* __restrict__ w1, const float* __restrict__ b1,
                           const float* __restrict__ w2, const float* __restrict__ b2,
                           const float* __restrict__ ln_g, const float* __restrict__ ln_b,
                           const float* __restrict__ sem_w, const float* __restrict__ sem_b,
                           const float* __restrict__ fast_w, const float* __restrict__ fast_b,
                           const float* __restrict__ slow_w, const float* __restrict__ slow_b)
{
    const int v = blockIdx.x;
    const int j = threadIdx.x;   // 0..127

    __shared__ float e[64];
    __shared__ float h1[128];
    __shared__ float x[64];
    __shared__ float xn[64];
    __shared__ float kk[64];

    if (j < 64) e[j] = embed[v * 64 + j];
    __syncthreads();

    // FFN1: h1[j] = relu(e . w1[:,j] + b1[j])
    {
        float a[8] = {0,0,0,0,0,0,0,0};
        #pragma unroll
        for (int d0 = 0; d0 < 64; d0 += 8)
            #pragma unroll
            for (int q = 0; q < 8; q++)
                a[q] = fmaf(e[d0 + q], w1[(d0 + q) * 128 + j], a[q]);
        float acc = ((a[0]+a[1])+(a[2]+a[3])) + ((a[4]+a[5])+(a[6]+a[7])) + b1[j];
        h1[j] = fmaxf(acc, 0.0f);
    }
    __syncthreads();

    // FFN2 + residual
    if (j < 64) {
        float a[8] = {0,0,0,0,0,0,0,0};
        #pragma unroll
        for (int d0 = 0; d0 < 128; d0 += 8)
            #pragma unroll
            for (int q = 0; q < 8; q++)
                a[q] = fmaf(h1[d0 + q], w2[(d0 + q) * 64 + j], a[q]);
        float acc = ((a[0]+a[1])+(a[2]+a[3])) + ((a[4]+a[5])+(a[6]+a[7])) + b2[j];
        x[j] = e[j] + acc;
    }
    __syncthreads();

    if (j < 64) {
        float mu = 0.0f;
        #pragma unroll
        for (int d = 0; d < 64; d++) mu += x[d];
        mu *= (1.0f / 64.0f);
        float var = 0.0f;
        #pragma unroll
        for (int d = 0; d < 64; d++) { float dd = x[d] - mu; var = fmaf(dd, dd, var); }
        var *= (1.0f / 64.0f);
        float r = rsqrtf(var + 1e-5f);
        xn[j] = (x[j] - mu) * r * ln_g[j] + ln_b[j];
    }
    __syncthreads();

    if (j < 64) {
        const float* wp; const float* bp; int cols, c;
        if (j < 32)      { wp = sem_w;  bp = sem_b;  cols = SD; c = j; }
        else if (j < 48) { wp = fast_w; bp = fast_b; cols = FD; c = j - 32; }
        else             { wp = slow_w; bp = slow_b; cols = FD; c = j - 48; }
        float a[8] = {0,0,0,0,0,0,0,0};
        #pragma unroll
        for (int d0 = 0; d0 < 64; d0 += 8)
            #pragma unroll
            for (int q = 0; q < 8; q++)
                a[q] = fmaf(xn[d0 + q], wp[(d0 + q) * cols + c], a[q]);
        float s = ((a[0]+a[1])+(a[2]+a[3])) + ((a[4]+a[5])+(a[6]+a[7])) + bp[c];
        kk[j] = s;
        g_lut[v * 64 + j] = s;
    }
    __syncthreads();

    if (j < 3) {
        const int lo = (j == 0) ? 0 : (j == 1) ? 32 : 48;
        const int hi = (j == 0) ? 32 : (j == 1) ? 48 : 64;
        float s = 0.0f;
        for (int d = lo; d < hi; d++) s = fmaf(kk[d], kk[d], s);
        g_inv[j * NVOC + v] = 1.0f / (s + 1e-6f);
    }
}

// ---------------------------------------------------------------------------
// Backward chunk (f32x2): adjoint vector recurrence, descending over chunk.
//   DIMP = f32 pairs (16 for sem, 8 for fast/slow)
//   SCALE 0: pacc bucket for c ;  SCALE 1/2: direct c accumulation
// ---------------------------------------------------------------------------
template<int DIMP, int SCALE>
__device__ __forceinline__ void bw_chunk2(u64t* __restrict__ u, u64t* __restrict__ c,
                                          float* __restrict__ pacc_row,
                                          int t_hi, int t_lo,
                                          const float* __restrict__ lut,
                                          const float* __restrict__ inv,
                                          const int* __restrict__ tokrow)
{
    const int off = (SCALE == 0) ? 0 : (SCALE == 1) ? 32 : 48;
    const float invL = 1.0f / 2048.0f;

    int tok = tokrow[t_hi - t_lo];
    u64t k[DIMP];
    {
        const ulonglong2* kb = reinterpret_cast<const ulonglong2*>(&lut[tok * 68 + off]);
        #pragma unroll
        for (int q = 0; q < DIMP / 2; q++) { ulonglong2 v = kb[q]; k[2*q] = v.x; k[2*q+1] = v.y; }
    }
    float ikk = inv[SCALE * 64 + tok];

    #pragma unroll 2
    for (int tt = t_hi; tt >= t_lo; tt--) {
        // prefetch next step
        const int nidx = (tt > t_lo) ? (tt - 1 - t_lo) : 0;
        const int ntok = tokrow[nidx];
        u64t kn[DIMP];
        {
            const ulonglong2* kb = reinterpret_cast<const ulonglong2*>(&lut[ntok * 68 + off]);
            #pragma unroll
            for (int q = 0; q < DIMP / 2; q++) { ulonglong2 v = kb[q]; kn[2*q] = v.x; kn[2*q+1] = v.y; }
        }
        const float ikkn = inv[SCALE * 64 + ntok];

        // d = k . u
        u64t a0 = 0ull, a1 = 0ull, a2 = 0ull, a3 = 0ull;
        #pragma unroll
        for (int i = 0; i < DIMP; i += 4) {
            a0 = ffma2(k[i+0], u[i+0], a0);
            a1 = ffma2(k[i+1], u[i+1], a1);
            a2 = ffma2(k[i+2], u[i+2], a2);
            a3 = ffma2(k[i+3], u[i+3], a3);
        }
        u64t s = fadd2(fadd2(a0, a1), fadd2(a2, a3));
        float slo, shi; unpack2(s, slo, shi);
        const float d = slo + shi;

        float p;
        if (SCALE == 0)       p = d;
        else if (SCALE == 1)  p = d * ((float)(tt + 1) * invL);
        else                  p = d * sqrtf((float)(tt + 1) * invL);

        if (SCALE == 0) {
            pacc_row[tok] += p;
        } else {
            const u64t p2 = pack2(p, p);
            #pragma unroll
            for (int i = 0; i < DIMP; i++) c[i] = ffma2(p2, k[i], c[i]);
        }

        const float qq = p * ikk;
        const u64t nq = pack2(-qq, -qq);
        #pragma unroll
        for (int i = 0; i < DIMP; i++) u[i] = ffma2(nq, k[i], u[i]);

        #pragma unroll
        for (int i = 0; i < DIMP; i++) k[i] = kn[i];
        tok = ntok; ikk = ikkn;
    }
}

// ---------------------------------------------------------------------------
// Kernel 2: one wave of 136 blocks
//   blocks 0..127  : forward matrix scan (f32x2), 2 batches/block
//   blocks 128..135: backward adjoint (f32x2), 32 batches/block, dbl-buffered
// ---------------------------------------------------------------------------
__global__ void __launch_bounds__(128)
scan_kernel(const int* __restrict__ seq)
{
    __shared__ __align__(16) char raw[44032];
    const int tid  = threadIdx.x;
    const int w    = tid >> 5;
    const int lane = tid & 31;

    if (blockIdx.x < NFWD) {
        // ========================= FORWARD =========================
        float* s_lut = (float*)raw;                    // 16384 B
        float* s_inv = (float*)(raw + 16384);          // 768 B
        int*   s_seq = (int*)  (raw + 17152);          // 2*(FSPLIT+1) ints

        const int b0 = blockIdx.x * 2;
        for (int i = tid; i < NVOC * 64; i += 128) s_lut[i] = g_lut[i];
        for (int i = tid; i < 3 * NVOC;  i += 128) s_inv[i] = g_inv[i];
        for (int i = tid; i < FSPLIT; i += 128) {
            s_seq[i]              = seq[ b0      * SEQL + i];
            s_seq[FSPLIT + 1 + i] = seq[(b0 + 1) * SEQL + i];
        }
        if (tid == 0) { s_seq[FSPLIT] = 0; s_seq[2 * FSPLIT + 1] = 0; }
        __syncthreads();

        const int  bsel = w >> 1;
        const int  b    = b0 + bsel;
        const int* sq   = s_seq + bsel * (FSPLIT + 1);

        if ((w & 1) == 0) {
            // ---- Ms 32x32 (16 f32x2 pairs/row), lane = row ----
            u64t m[16];
            #pragma unroll
            for (int j = 0; j < 16; j++) m[j] = 0ull;

            int tok = sq[0];
            u64t k[16]; float ki, ikk;
            {
                const ulonglong2* kp = reinterpret_cast<const ulonglong2*>(&s_lut[tok * 64]);
                #pragma unroll
                for (int q = 0; q < 8; q++) { ulonglong2 v = kp[q]; k[2*q] = v.x; k[2*q+1] = v.y; }
                ki  = s_lut[tok * 64 + lane];
                ikk = s_inv[tok];
            }

            #pragma unroll 2
            for (int t = 0; t < FSPLIT; t++) {
                const int ntok = sq[t + 1];
                u64t kn[16]; float kin, ikkn;
                {
                    const ulonglong2* kp = reinterpret_cast<const ulonglong2*>(&s_lut[ntok * 64]);
                    #pragma unroll
                    for (int q = 0; q < 8; q++) { ulonglong2 v = kp[q]; kn[2*q] = v.x; kn[2*q+1] = v.y; }
                    kin  = s_lut[ntok * 64 + lane];
                    ikkn = s_inv[ntok];
                }

                u64t a0 = 0ull, a1 = 0ull, a2 = 0ull, a3 = 0ull;
                #pragma unroll
                for (int j = 0; j < 16; j += 4) {
                    a0 = ffma2(m[j+0], k[j+0], a0);
                    a1 = ffma2(m[j+1], k[j+1], a1);
                    a2 = ffma2(m[j+2], k[j+2], a2);
                    a3 = ffma2(m[j+3], k[j+3], a3);
                }
                u64t s = fadd2(fadd2(a0, a1), fadd2(a2, a3));
                float slo, shi; unpack2(s, slo, shi);
                const float vp = slo + shi;
                const float dv = fmaf(-vp, ikk, ki);
                const u64t dv2 = pack2(dv, dv);
                #pragma unroll
                for (int j = 0; j < 16; j++) m[j] = ffma2(dv2, k[j], m[j]);

                #pragma unroll
                for (int j = 0; j < 16; j++) k[j] = kn[j];
                ki = kin; ikk = ikkn;
            }

            u64t* dst = reinterpret_cast<u64t*>(&g_Ms[(b * SD + lane) * SD]);
            #pragma unroll
            for (int q = 0; q < 16; q++) dst[q] = m[q];
        } else {
            // ---- Mef (lanes 0-15) / Mes (lanes 16-31), 8 pairs/row ----
            const bool isf = (lane < 16);
            const int  r   = lane & 15;
            const int  off = isf ? 32 : 48;
            const float* invp = s_inv + (isf ? 64 : 128);
            const float invL = 1.0f / 2048.0f;

            u64t m[8];
            #pragma unroll
            for (int j = 0; j < 8; j++) m[j] = 0ull;

            int tok = sq[0];
            u64t k[8]; float kr, ikk;
            {
                const ulonglong2* kp = reinterpret_cast<const ulonglong2*>(&s_lut[tok * 64 + off]);
                #pragma unroll
                for (int q = 0; q < 4; q++) { ulonglong2 v = kp[q]; k[2*q] = v.x; k[2*q+1] = v.y; }
                kr  = s_lut[tok * 64 + off + r];
                ikk = invp[tok];
            }

            #pragma unroll 2
            for (int t = 0; t < FSPLIT; t++) {
                const int ntok = sq[t + 1];
                u64t kn[8]; float krn, ikkn;
                {
                    const ulonglong2* kp = reinterpret_cast<const ulonglong2*>(&s_lut[ntok * 64 + off]);
                    #pragma unroll
                    for (int q = 0; q < 4; q++) { ulonglong2 v = kp[q]; kn[2*q] = v.x; kn[2*q+1] = v.y; }
                    krn  = s_lut[ntok * 64 + off + r];
                    ikkn = invp[ntok];
                }

                float wt = (float)(t + 1) * invL;
                if (!isf) wt = sqrtf(wt);

                u64t a0 = 0ull, a1 = 0ull;
                #pragma unroll
                for (int j = 0; j < 8; j += 2) {
                    a0 = ffma2(m[j+0], k[j+0], a0);
                    a1 = ffma2(m[j+1], k[j+1], a1);
                }
                u64t s = fadd2(a0, a1);
                float slo, shi; unpack2(s, slo, shi);
                const float vp  = slo + shi;
                const float dv  = fmaf(-vp, ikk, kr);
                const float wdv = wt * dv;
                const u64t dv2 = pack2(wdv, wdv);
                #pragma unroll
                for (int j = 0; j < 8; j++) m[j] = ffma2(dv2, k[j], m[j]);

                #pragma unroll
                for (int j = 0; j < 8; j++) k[j] = kn[j];
                kr = krn; ikk = ikkn;
            }

            float* basep = isf ? g_Mef : g_Mes;
            u64t* dst = reinterpret_cast<u64t*>(&basep[(b * FD + r) * FD]);
            #pragma unroll
            for (int q = 0; q < 8; q++) dst[q] = m[q];
        }
    } else {
        // ========================= BACKWARD =========================
        float* s_lutP = (float*)raw;                    // 64*68*4 = 17408
        float* s_invB = (float*)(raw + 17408);          // 768
        int*   s_tok  = (int*)  (raw + 18176);          // 2 * 32*68 ints = 17408
        float* s_pacc = (float*)(raw + 35584);          // 32*65*4 = 8320

        const int bb = blockIdx.x - NFWD;               // 0..7
        const int b0 = bb * 32;
        const int b  = b0 + lane;

        for (int i = tid; i < NVOC * 64; i += 128) {
            const int rr = i >> 6, cc = i & 63;
            s_lutP[rr * 68 + cc] = g_lut[i];
        }
        for (int i = tid; i < 3 * NVOC; i += 128) s_invB[i] = g_inv[i];
        for (int i = tid; i < 32 * 65; i += 128) s_pacc[i] = 0.0f;

        // stage top chunk (all threads): chunk ci covers [FSPLIT+64ci, +64)
        {
            const int base = FSPLIT + 64 * (NCHUNK - 1);
            const int buf  = (NCHUNK - 1) & 1;
            for (int i = tid; i < 32 * 16; i += 128) {
                const int bbx = i >> 4, q = i & 15;
                *reinterpret_cast<int4*>(&s_tok[buf * 32 * 68 + bbx * 68 + q * 4]) =
                    *reinterpret_cast<const int4*>(&seq[(b0 + bbx) * SEQL + base + q * 4]);
            }
        }
        __syncthreads();

        // init u = k(query token), c = 0
        u64t u[16], c[16];
        if (w < 3) {
            const int off = (w == 0) ? 0 : (w == 1) ? 32 : 48;
            const int dimp = (w == 0) ? 16 : 8;
            const int tokq = __ldg(&seq[b * SEQL + SEQL - 1]);
            const ulonglong2* kp = reinterpret_cast<const ulonglong2*>(&s_lutP[tokq * 68 + off]);
            for (int q = 0; q < dimp / 2; q++) { ulonglong2 v = kp[q]; u[2*q] = v.x; u[2*q+1] = v.y; }
            for (int i = 0; i < 16; i++) c[i] = 0ull;
        }

        float* pacc_row = &s_pacc[lane * 65];

        for (int ci = NCHUNK - 1; ci >= 0; ci--) {
            const int c_lo = FSPLIT + 64 * ci;
            const int t_hi = (c_lo + 63 < NSTEP - 1) ? (c_lo + 63) : (NSTEP - 1);
            const int buf  = ci & 1;
            const int* tokrow = &s_tok[buf * 32 * 68 + lane * 68];

            if (w == 3) {
                if (ci > 0) {
                    const int nbase = FSPLIT + 64 * (ci - 1);
                    const int nbuf  = (ci - 1) & 1;
                    for (int i = lane; i < 32 * 16; i += 32) {
                        const int bbx = i >> 4, q = i & 15;
                        *reinterpret_cast<int4*>(&s_tok[nbuf * 32 * 68 + bbx * 68 + q * 4]) =
                            *reinterpret_cast<const int4*>(&seq[(b0 + bbx) * SEQL + nbase + q * 4]);
                    }
                }
            } else if (w == 0) {
                bw_chunk2<16, 0>(u, c, pacc_row, t_hi, c_lo, s_lutP, s_invB, tokrow);
            } else if (w == 1) {
                bw_chunk2<8, 1>(u, c, pacc_row, t_hi, c_lo, s_lutP, s_invB, tokrow);
            } else {
                bw_chunk2<8, 2>(u, c, pacc_row, t_hi, c_lo, s_lutP, s_invB, tokrow);
            }
            __syncthreads();
        }

        // sem: reconstruct c from vocab buckets
        if (w == 0) {
            #pragma unroll 4
            for (int v = 0; v < NVOC; v++) {
                const float pv = pacc_row[v];
                const u64t p2 = pack2(pv, pv);
                const ulonglong2* kp = reinterpret_cast<const ulonglong2*>(&s_lutP[v * 68]);
                #pragma unroll
                for (int q = 0; q < 8; q++) {
                    ulonglong2 kv = kp[q];
                    c[2*q]   = ffma2(p2, kv.x, c[2*q]);
                    c[2*q+1] = ffma2(p2, kv.y, c[2*q+1]);
                }
            }
        }

        if (w < 3) {
            const int off = (w == 0) ? 0 : (w == 1) ? 32 : 48;
            const int dimp = (w == 0) ? 16 : 8;
            u64t* up = reinterpret_cast<u64t*>(&g_u [b * 64 + off]);
            u64t* cp = reinterpret_cast<u64t*>(&g_ct[b * 64 + off]);
            for (int q = 0; q < dimp; q++) { up[q] = u[q]; cp[q] = c[q]; }
        }
    }
}

// ---------------------------------------------------------------------------
// Kernel 3: join  c = M_F u_F + c_tail , then readout GEMM
// ---------------------------------------------------------------------------
__global__ void __launch_bounds__(64)
join_kernel(const float* __restrict__ out_w, const float* __restrict__ out_b,
            float* __restrict__ out)
{
    __shared__ float su[64];
    __shared__ float sc[64];
    const int b   = blockIdx.x;
    const int tid = threadIdx.x;

    su[tid] = g_u[b * 64 + tid];
    __syncthreads();

    float acc = g_ct[b * 64 + tid];
    if (tid < 32) {
        const float4* mp = reinterpret_cast<const float4*>(&g_Ms[(b * SD + tid) * SD]);
        #pragma unroll
        for (int q = 0; q < 8; q++) {
            float4 mv = mp[q];
            acc = fmaf(mv.x, su[4*q+0], acc);
            acc = fmaf(mv.y, su[4*q+1], acc);
            acc = fmaf(mv.z, su[4*q+2], acc);
            acc = fmaf(mv.w, su[4*q+3], acc);
        }
    } else if (tid < 48) {
        const int r = tid - 32;
        const float4* mp = reinterpret_cast<const float4*>(&g_Mef[(b * FD + r) * FD]);
        #pragma unroll
        for (int q = 0; q < 4; q++) {
            float4 mv = mp[q];
            acc = fmaf(mv.x, su[32 + 4*q+0], acc);
            acc = fmaf(mv.y, su[32 + 4*q+1], acc);
            acc = fmaf(mv.z, su[32 + 4*q+2], acc);
            acc = fmaf(mv.w, su[32 + 4*q+3], acc);
        }
    } else {
        const int r = tid - 48;
        const float4* mp = reinterpret_cast<const float4*>(&g_Mes[(b * FD + r) * FD]);
        #pragma unroll
        for (int q = 0; q < 4; q++) {
            float4 mv = mp[q];
            acc = fmaf(mv.x, su[48 + 4*q+0], acc);
            acc = fmaf(mv.y, su[48 + 4*q+1], acc);
            acc = fmaf(mv.z, su[48 + 4*q+2], acc);
            acc = fmaf(mv.w, su[48 + 4*q+3], acc);
        }
    }
    sc[tid] = acc;
    __syncthreads();

    float o = out_b[tid];
    #pragma unroll 8
    for (int d = 0; d < 64; d++) o = fmaf(sc[d], out_w[d * 64 + tid], o);
    out[b * 64 + tid] = o;
}

// ---------------------------------------------------------------------------
extern "C" void kernel_launch(void* const* d_in, const int* in_sizes, int n_in,
                              void* d_out, int out_size)
{
    const int*   seq    = (const int*)  d_in[0];
    const float* embed  = (const float*)d_in[1];
    const float* w1     = (const float*)d_in[2];
    const float* b1     = (const float*)d_in[3];
    const float* w2     = (const float*)d_in[4];
    const float* b2     = (const float*)d_in[5];
    const float* ln_g   = (const float*)d_in[6];
    const float* ln_b   = (const float*)d_in[7];
    const float* sem_w  = (const float*)d_in[8];
    const float* sem_b  = (const float*)d_in[9];
    const float* fast_w = (const float*)d_in[10];
    const float* fast_b = (const float*)d_in[11];
    const float* slow_w = (const float*)d_in[12];
    const float* slow_b = (const float*)d_in[13];
    const float* out_w  = (const float*)d_in[14];
    const float* out_b  = (const float*)d_in[15];
    float* out = (float*)d_out;

    lut_kernel<<<NVOC, 128>>>(embed, w1, b1, w2, b2, ln_g, ln_b,
                              sem_w, sem_b, fast_w, fast_b, slow_w, slow_b);
    scan_kernel<<<NFWD + NBWD, 128>>>(seq);
    join_kernel<<<NB, 64>>>(out_w, out_b, out);
}